// round 14
// baseline (speedup 1.0000x reference)
#include <cuda_runtime.h>
#include <math.h>

// ---------------- problem constants ----------------
#define NB    4
#define NLVL  3
#define NA    9
#define NC    80
#define PRE   1000
#define TOPN  100
#define NCAP  8192
#define SPECMAX 2048
#define SORTMAX 4096
#define NR    1024        // NMS mask restricted to top-NR rows
#define NCHR  16          // NR/64 words
#define MT    8           // NR/128 tiles per dim
#define NTRI  36          // MT*(MT+1)/2
#define CHUNK 1000        // float4 per TMA chunk
#define CBYTES (CHUNK * 16)
#define LOG_MAX_F 4.135166556742356f
#define IMG_OFF 641.0f

typedef unsigned long long u64;

// Precomputed anchors (verified bit-exact since R5, rel_err 2.455e-8)
__constant__ float c_AW[3][9] = {
    { 44.f,  88.f, 176.f,  32.f,  64.f, 128.f,  24.f,  48.f,  96.f},
    { 92.f, 184.f, 368.f,  64.f, 128.f, 256.f,  44.f,  88.f, 176.f},
    {180.f, 360.f, 720.f, 128.f, 256.f, 512.f,  92.f, 184.f, 368.f}};
__constant__ float c_AH[3][9] = {
    { 24.f,  48.f,  96.f,  32.f,  64.f, 128.f,  48.f,  96.f, 192.f},
    { 48.f,  96.f, 192.f,  64.f, 128.f, 256.f,  88.f, 176.f, 352.f},
    { 88.f, 176.f, 352.f, 128.f, 256.f, 512.f, 184.f, 368.f, 736.f}};
__constant__ float c_ctr[3] = {3.5f, 7.5f, 15.5f};

// ---------------- device scratch (zero at load; re-zeroed each replay by reduce kernel) ----------------
__device__ unsigned int g_cnt  [12];
__device__ unsigned int g_done [12];
__device__ unsigned int g_need [12];
__device__ unsigned int g_mdone[NB];
__device__ u64          g_cand[12][NCAP];
__device__ float        g_rois[NB][3000][6];
__device__ u64          g_skey[NB][3000];
__device__ int          g_spos[NB][3008];
__device__ float        g_sx1[NB][3008], g_sy1[NB][3008], g_sx2[NB][3008], g_sy2[NB][3008], g_sar[NB][3008];
__device__ __align__(16) u64 g_mask[NB][NR * NCHR];

// ---------------- PTX helpers ----------------
__device__ __forceinline__ unsigned sptr(const void* p) {
    return (unsigned)__cvta_generic_to_shared(p);
}
#define MBAR_INIT(a, c) \
    asm volatile("mbarrier.init.shared.b64 [%0], %1;" :: "r"(a), "r"(c) : "memory")
#define MBAR_EXPECT(a, bytes) \
    asm volatile("mbarrier.arrive.expect_tx.shared.b64 _, [%0], %1;" :: "r"(a), "r"((unsigned)(bytes)) : "memory")
#define BULK_G2S(dst, src, bytes, mbar) \
    asm volatile("cp.async.bulk.shared::cluster.global.mbarrier::complete_tx::bytes [%0], [%1], %2, [%3];" \
        :: "r"(dst), "l"(src), "r"((unsigned)(bytes)), "r"(mbar) : "memory")

__device__ __forceinline__ void mbar_wait(unsigned mbar, unsigned parity) {
    unsigned done;
    asm volatile(
        "{\n\t.reg .pred p;\n\t"
        "mbarrier.try_wait.parity.acquire.cta.shared::cta.b64 p, [%1], %2;\n\t"
        "selp.b32 %0, 1, 0, p;\n\t}"
        : "=r"(done) : "r"(mbar), "r"(parity) : "memory");
    if (!done) {
        asm volatile(
            "{\n\t.reg .pred P1;\n\t"
            "WL_%=:\n\t"
            "mbarrier.try_wait.parity.acquire.cta.shared::cta.b64 P1, [%0], %1, 0x989680;\n\t"
            "@P1 bra.uni WD_%=;\n\t"
            "bra.uni WL_%=;\n\t"
            "WD_%=:\n\t}"
            :: "r"(mbar), "r"(parity) : "memory");
    }
}

// ---------------- helpers ----------------
__device__ __forceinline__ void bitonic_desc(u64* s, int n, int tid, int nt) {
    for (int k = 2; k <= n; k <<= 1) {
        for (int j = k >> 1; j > 0; j >>= 1) {
            for (int i = tid; i < n; i += nt) {
                int ixj = i ^ j;
                if (ixj > i) {
                    u64 a = s[i], b = s[ixj];
                    bool sw = ((i & k) == 0) ? (a < b) : (a > b);
                    if (sw) { s[i] = b; s[ixj] = a; }
                }
            }
            __syncthreads();
        }
    }
}

template<int HW>
__device__ __forceinline__ void push_cand_t(int id, int m, float x) {
    int ch = m / HW;
    int pp = m - ch * HW;
    int a  = ch / NC;
    int cc = ch - a * NC;
    unsigned int f = (unsigned int)((pp * NA + a) * NC + cc);
    float score = 1.0f / (1.0f + expf(-x));
    u64 k64 = ((u64)__float_as_uint(score) << 32) | (u64)(0xFFFFFFFFu - f);
    unsigned int pos = atomicAdd(&g_cnt[id], 1u);
    if (pos < NCAP) g_cand[id][pos] = k64;
}

__device__ __forceinline__ void push_cand(int id, int m, int HW, float x) {
    int ch = m / HW;
    int pp = m - ch * HW;
    int a  = ch / NC;
    int cc = ch - a * NC;
    unsigned int f = (unsigned int)((pp * NA + a) * NC + cc);
    float score = 1.0f / (1.0f + expf(-x));
    u64 k64 = ((u64)__float_as_uint(score) << 32) | (u64)(0xFFFFFFFFu - f);
    unsigned int pos = atomicAdd(&g_cnt[id], 1u);
    if (pos < NCAP) g_cand[id][pos] = k64;
}

// ---------------- kernel 1: TMA bulk-copy double-buffered streaming gather ----------------
template<int LVL, int PER, int NVEC, int HW, int NCHK>
__device__ __forceinline__ void stream_level_tma(const float4* __restrict__ cls, int li, float specT) {
    int b = li / PER;
    int chunk0 = li - b * PER;
    constexpr int LEN = NVEC / PER;                // 4000 or 3000 float4
    int base_idx = chunk0 * LEN;                   // float4 index within image
    const float4* p = cls + (size_t)b * NVEC + (size_t)base_idx;
    int id = b * 3 + LVL;
    int tid = threadIdx.x;

    __shared__ __align__(16) float4 buf[2][CHUNK];
    __shared__ __align__(8)  u64 mbar[2];

    if (tid == 0) {
        MBAR_INIT(sptr(&mbar[0]), 1);
        MBAR_INIT(sptr(&mbar[1]), 1);
    }
    __syncthreads();

    if (tid == 0) {
#pragma unroll
        for (int c = 0; c < 2; c++) {
            if (c < NCHK) {
                MBAR_EXPECT(sptr(&mbar[c]), CBYTES);
                BULK_G2S(sptr(buf[c]), (const void*)(p + c * CHUNK), CBYTES, sptr(&mbar[c]));
            }
        }
    }

#pragma unroll
    for (int c = 0; c < NCHK; c++) {
        int bi = c & 1;
        unsigned ph = (unsigned)((c >> 1) & 1);
        mbar_wait(sptr(&mbar[bi]), ph);

        // process chunk from smem
        for (int j = tid; j < CHUNK; j += 256) {
            float4 v = buf[bi][j];
            float m4 = fmaxf(fmaxf(v.x, v.y), fmaxf(v.z, v.w));
            if (m4 >= specT) {
                int idx = base_idx + c * CHUNK + j;
                float cc4[4] = {v.x, v.y, v.z, v.w};
#pragma unroll
                for (int q = 0; q < 4; q++)
                    if (cc4[q] >= specT) push_cand_t<HW>(id, idx * 4 + q, cc4[q]);
            }
        }
        __syncthreads();
        if (tid == 0 && c + 2 < NCHK) {
            MBAR_EXPECT(sptr(&mbar[bi]), CBYTES);
            BULK_G2S(sptr(buf[bi]), (const void*)(p + (c + 2) * CHUNK), CBYTES, sptr(&mbar[bi]));
        }
    }

    __syncthreads();
    if (tid == 0) {
        __threadfence();
        unsigned int o = atomicAdd(&g_done[id], 1u);
        if (o == (unsigned int)(PER - 1)) {
            unsigned int cnt = g_cnt[id];
            int ok = (cnt >= PRE && cnt <= SPECMAX);
            g_need[id] = ok ? 0u : 1u;
            if (!ok) g_cnt[id] = 0;
        }
    }
}

__global__ void __launch_bounds__(256)
passA_kernel(const float4* __restrict__ c0,
             const float4* __restrict__ c1,
             const float4* __restrict__ c2) {
    int bx = blockIdx.x;
    if (bx < 1152)      stream_level_tma<0, 288, 1152000, 6400, 4>(c0, bx,        3.42f);
    else if (bx < 1440) stream_level_tma<1, 72,  288000,  1600, 4>(c1, bx - 1152, 3.02f);
    else                stream_level_tma<2, 24,  72000,   400,  3>(c2, bx - 1440, 2.575f);
}

// ---------------- kernel 2: (rare exact fallback) + sort + fp32 decode + elected merge ----------------
__global__ void topk_decode_kernel(const float4* __restrict__ c0,
                                   const float4* __restrict__ c1,
                                   const float4* __restrict__ c2,
                                   const float* __restrict__ loc0,
                                   const float* __restrict__ loc1,
                                   const float* __restrict__ loc2,
                                   const float* __restrict__ info) {
    extern __shared__ u64 sk[];      // 32KB dynamic
    int lvl = blockIdx.x % 3, b = blockIdx.x / 3;
    int id = b * 3 + lvl;
    int tid = threadIdx.x, nt = blockDim.x;
    const int Wt[3] = {80, 40, 20};
    const int St[3] = {8, 16, 32};
    const int Nv[3] = {1152000, 288000, 72000};
    int W = Wt[lvl], stride = St[lvl];
    const float* loc = (lvl == 0) ? loc0 : ((lvl == 1) ? loc1 : loc2);
    int HW = W * W;

    if (g_need[id] != 0u) {
        unsigned int* hist = (unsigned int*)sk;
        __shared__ unsigned int segsum[256];
        __shared__ unsigned int s_thr;
        int nvec = Nv[lvl];
        const float4* p = ((lvl == 0) ? c0 : ((lvl == 1) ? c1 : c2)) + (size_t)b * nvec;

        for (int i = tid; i < 4096; i += nt) hist[i] = 0;
        __syncthreads();
        for (int i = tid; i < nvec; i += nt) {
            float4 v = p[i];
            float c[4] = {v.x, v.y, v.z, v.w};
#pragma unroll
            for (int q = 0; q < 4; q++) {
                if (c[q] >= 1.0f) {
                    unsigned int key = __float_as_uint(c[q]) | 0x80000000u;
                    atomicAdd(&hist[key >> 20], 1u);
                }
            }
        }
        __syncthreads();
        if (tid < 256) {
            unsigned int s = 0;
#pragma unroll
            for (int q = 0; q < 16; q++) s += hist[tid * 16 + q];
            segsum[tid] = s;
        }
        __syncthreads();
        for (int d = 1; d < 256; d <<= 1) {
            unsigned int v = 0;
            if (tid < 256) {
                v = segsum[tid];
                if (tid + d < 256) v += segsum[tid + d];
            }
            __syncthreads();
            if (tid < 256) segsum[tid] = v;
            __syncthreads();
        }
        if (tid < 256) {
            unsigned int cum = (tid < 255) ? segsum[tid + 1] : 0u;
            for (int q = 15; q >= 0; q--) {
                int bin = tid * 16 + q;
                unsigned int hv = hist[bin];
                cum += hv;
                if (cum >= PRE && (cum - hv) < PRE) s_thr = ((unsigned int)bin) << 20;
            }
        }
        __syncthreads();
        unsigned int thr = s_thr;
        for (int i = tid; i < nvec; i += nt) {
            float4 v = p[i];
            float c[4] = {v.x, v.y, v.z, v.w};
#pragma unroll
            for (int q = 0; q < 4; q++) {
                if (c[q] >= 1.0f) {
                    unsigned int key = __float_as_uint(c[q]) | 0x80000000u;
                    if (key >= thr) push_cand(id, i * 4 + q, HW, c[q]);
                }
            }
        }
        __syncthreads();
    }

    unsigned int cnt = atomicAdd(&g_cnt[id], 0u);
    if (cnt > SORTMAX) cnt = SORTMAX;
    int n = 1024;
    while (n < (int)cnt) n <<= 1;
    for (int i = tid; i < n; i += nt)
        sk[i] = (i < (int)cnt) ? g_cand[id][i] : 0ull;
    __syncthreads();
    bitonic_desc(sk, n, tid, nt);

    float imh = info[b * 5 + 0];
    float imw = info[b * 5 + 1];
    float ctr = c_ctr[lvl];

    for (int r = tid; r < PRE; r += nt) {
        u64 key = sk[r];
        int mpos = lvl * PRE + r;
        float* row = g_rois[b][mpos];
        if (key == 0ull) {
            row[0] = row[1] = row[2] = row[3] = row[4] = row[5] = 0.0f;
            g_skey[b][mpos] = (u64)(0xFFFFFFFFu - (unsigned int)mpos);
            continue;
        }
        unsigned int f = 0xFFFFFFFFu - (unsigned int)(key & 0xFFFFFFFFu);
        float score = __uint_as_float((unsigned int)(key >> 32));
        g_skey[b][mpos] = ((u64)__float_as_uint(score) << 32) |
                          (u64)(0xFFFFFFFFu - (unsigned int)mpos);
        int aidx = f / NC;
        int cc = f - aidx * NC;
        int pp = aidx / NA;
        int a = aidx - pp * NA;
        int hh = pp / W;
        int ww = pp - hh * W;

        float ws = c_AW[lvl][a];
        float hs = c_AH[lvl][a];
        float cx = (float)(ww * stride) + ctr;
        float cy = (float)(hh * stride) + ctr;

        size_t lbase = ((size_t)b * (NA * 4) + (size_t)a * 4) * (size_t)HW + (size_t)pp;
        float dx = loc[lbase];
        float dy = loc[lbase + HW];
        float dw = loc[lbase + 2 * (size_t)HW];
        float dh = loc[lbase + 3 * (size_t)HW];

        dw = fminf(fmaxf(dw, -LOG_MAX_F), LOG_MAX_F);
        dh = fminf(fmaxf(dh, -LOG_MAX_F), LOG_MAX_F);
        float pcx = dx * ws + cx, pcy = dy * hs + cy;
        float pw = expf(dw) * ws, ph = expf(dh) * hs;
        float x1 = pcx - 0.5f * (pw - 1.0f);
        float y1 = pcy - 0.5f * (ph - 1.0f);
        float x2 = pcx + 0.5f * (pw - 1.0f);
        float y2 = pcy + 0.5f * (ph - 1.0f);
        x1 = fminf(fmaxf(x1, 0.0f), imw - 1.0f);
        y1 = fminf(fmaxf(y1, 0.0f), imh - 1.0f);
        x2 = fminf(fmaxf(x2, 0.0f), imw - 1.0f);
        y2 = fminf(fmaxf(y2, 0.0f), imh - 1.0f);

        row[0] = x1; row[1] = y1; row[2] = x2; row[3] = y2;
        row[4] = score;
        row[5] = (float)(cc + 1);
    }

    __syncthreads();
    __shared__ int s_lastm;
    if (tid == 0) {
        __threadfence();
        unsigned int o = atomicAdd(&g_mdone[b], 1u);
        s_lastm = (o == 2u);
    }
    __syncthreads();
    if (!s_lastm) return;
    __threadfence();

    u64* A = sk;
    for (int i = tid; i < 3000; i += nt) A[i] = g_skey[b][i];
    __syncthreads();
    for (int i = tid; i < 3000; i += nt) {
        u64 k = A[i];
        int l = i / 1000;
        int r = i - l * 1000;
        int rank = r;
#pragma unroll
        for (int o = 0; o < 3; o++) {
            if (o == l) continue;
            const u64* arr = &A[o * 1000];
            int lo = 0, hi = 1000;
            while (lo < hi) {
                int mid = (lo + hi) >> 1;
                if (arr[mid] > k) lo = mid + 1; else hi = mid;
            }
            rank += lo;
        }
        g_spos[b][rank] = i;
        const float* rw = g_rois[b][i];
        float off = rw[5] * IMG_OFF;
        float a1 = rw[0] + off, b1 = rw[1] + off;
        float a2 = rw[2] + off, b2 = rw[3] + off;
        g_sx1[b][rank] = a1; g_sy1[b][rank] = b1;
        g_sx2[b][rank] = a2; g_sy2[b][rank] = b2;
        g_sar[b][rank] = (a2 - a1 + 1.0f) * (b2 - b1 + 1.0f);
    }
}

// ---------------- kernel 3: lean suppression bitmask, NO dynamic smem (dense packing) ----------------
__global__ void __launch_bounds__(128) mask_kernel() {
    int b = blockIdx.y;
    int t = blockIdx.x;
    int tr = 0;
    while (t >= MT - tr) { t -= MT - tr; tr++; }
    int tc = tr + t;
    int tid = threadIdx.x;

    __shared__ float sx1[128], sy1[128], sx2[128], sy2[128], sar[128];
    int col0 = tc * 128;
    int c = col0 + tid;
    sx1[tid] = g_sx1[b][c];
    sy1[tid] = g_sy1[b][c];
    sx2[tid] = g_sx2[b][c];
    sy2[tid] = g_sy2[b][c];
    sar[tid] = g_sar[b][c];
    __syncthreads();

    int row = tr * 128 + tid;
    float X1 = g_sx1[b][row], Y1 = g_sy1[b][row];
    float X2 = g_sx2[b][row], Y2 = g_sy2[b][row];
    float AR = g_sar[b][row];
    u64 bits0 = 0ull, bits1 = 0ull;
#pragma unroll 4
    for (int j = 0; j < 128; j++) {
        int cidx = col0 + j;
        if (cidx <= row) continue;
        float ltx = fmaxf(X1, sx1[j]);
        float lty = fmaxf(Y1, sy1[j]);
        float rbx = fminf(X2, sx2[j]);
        float rby = fminf(Y2, sy2[j]);
        float w = fmaxf((rbx - ltx) + 1.0f, 0.0f);
        float h = fmaxf((rby - lty) + 1.0f, 0.0f);
        float inter = w * h;
        float iou = inter / ((AR + sar[j]) - inter);
        if (iou > 0.5f) {
            if (j < 64) bits0 |= (1ull << j);
            else        bits1 |= (1ull << (j - 64));
        }
    }
    int ci0 = 2 * tc;
    g_mask[b][row * NCHR + ci0]     = bits0;
    g_mask[b][row * NCHR + ci0 + 1] = bits1;
}

// ---------------- kernel 4: smem-staged broadcast-LDS greedy scan + fallback + rezero ----------------
__global__ void __launch_bounds__(1024) reduce_kernel(float* __restrict__ out) {
    extern __shared__ u64 smask[];        // NR*NCHR u64 = 128KB dynamic
    int b = blockIdx.x, tid = threadIdx.x;

    {
        const ulonglong2* src = (const ulonglong2*)g_mask[b];
        ulonglong2* dst = (ulonglong2*)smask;
        for (int i = tid; i < NR * NCHR / 2; i += 1024)
            dst[i] = src[i];
    }
    __syncthreads();

    __shared__ int kept[TOPN];
    __shared__ int s_k;

    if (tid < 32) {
        const unsigned FULL = 0xFFFFFFFFu;
        int lane = tid;
        u64 myremv = 0ull;
        int k = 0;
        for (int w = 0; w < NCHR && k < TOPN; w++) {
            u64 avail = ~__shfl_sync(FULL, myremv, w);
            while (avail && k < TOPN) {
                int j = __ffsll((long long)avail) - 1;
                int i = w * 64 + j;
                kept[k] = i;
                k++;
                if (k == TOPN) break;
                u64 diagw = smask[(size_t)i * NCHR + w];
                u64 roww = (lane < NCHR) ? smask[(size_t)i * NCHR + lane] : 0ull;
                myremv |= roww;
                avail &= ~(1ull << j);
                avail &= ~diagw;
            }
        }
        if (lane == 0) s_k = k;
    }
    __syncthreads();
    int k = s_k;

    if (k == TOPN) {
        for (int r = tid; r < TOPN; r += 1024) {
            float* o = out + ((size_t)b * TOPN + r) * 7;
            int pos = g_spos[b][kept[r]];
            const float* rw = g_rois[b][pos];
            o[0] = (float)b;
            o[1] = rw[0]; o[2] = rw[1]; o[3] = rw[2]; o[4] = rw[3];
            o[5] = rw[4]; o[6] = rw[5];
        }
    } else {
        __shared__ unsigned char supp[3000];
        __shared__ int fkept[TOPN];
        __shared__ int s_i, s_k2, s_cur;
        for (int i = tid; i < 3000; i += 1024) supp[i] = 0;
        if (tid == 0) { s_i = 0; s_k2 = 0; }
        __syncthreads();
        for (;;) {
            if (tid == 0) {
                int i = s_i;
                while (i < 3000 && supp[i]) i++;
                if (i < 3000 && s_k2 < TOPN) {
                    fkept[s_k2] = i; s_k2++; s_i = i + 1; s_cur = i;
                } else s_cur = -1;
            }
            __syncthreads();
            int i = s_cur;
            if (i < 0) break;
            if (s_k2 >= TOPN) break;
            float X1 = g_sx1[b][i], Y1 = g_sy1[b][i];
            float X2 = g_sx2[b][i], Y2 = g_sy2[b][i], AR = g_sar[b][i];
            for (int j = i + 1 + tid; j < 3000; j += 1024) {
                if (supp[j]) continue;
                float ltx = fmaxf(X1, g_sx1[b][j]);
                float lty = fmaxf(Y1, g_sy1[b][j]);
                float rbx = fminf(X2, g_sx2[b][j]);
                float rby = fminf(Y2, g_sy2[b][j]);
                float w = fmaxf((rbx - ltx) + 1.0f, 0.0f);
                float h = fmaxf((rby - lty) + 1.0f, 0.0f);
                float inter = w * h;
                float iou = inter / ((AR + g_sar[b][j]) - inter);
                if (iou > 0.5f) supp[j] = 1;
            }
            __syncthreads();
        }
        __syncthreads();
        for (int r = tid; r < TOPN; r += 1024) {
            float* o = out + ((size_t)b * TOPN + r) * 7;
            if (r < s_k2) {
                int pos = g_spos[b][fkept[r]];
                const float* rw = g_rois[b][pos];
                o[0] = (float)b;
                o[1] = rw[0]; o[2] = rw[1]; o[3] = rw[2]; o[4] = rw[3];
                o[5] = rw[4]; o[6] = rw[5];
            } else {
                for (int q = 0; q < 7; q++) o[q] = 0.0f;
            }
        }
        __syncthreads();
    }

    if (tid == 0) {
        g_mdone[b] = 0;
#pragma unroll
        for (int l = 0; l < 3; l++) {
            g_cnt[b * 3 + l] = 0;
            g_done[b * 3 + l] = 0;
            g_need[b * 3 + l] = 0;
        }
    }
}

// ---------------- host launcher ----------------
extern "C" void kernel_launch(void* const* d_in, const int* in_sizes, int n_in,
                              void* d_out, int out_size) {
    (void)in_sizes; (void)n_in; (void)out_size;
    const float4* cls0 = (const float4*)d_in[0];
    const float*  loc0 = (const float*)d_in[1];
    const float4* cls1 = (const float4*)d_in[2];
    const float*  loc1 = (const float*)d_in[3];
    const float4* cls2 = (const float4*)d_in[4];
    const float*  loc2 = (const float*)d_in[5];
    const float*  info = (const float*)d_in[6];
    float* out = (float*)d_out;

    cudaFuncSetAttribute(topk_decode_kernel,
                         cudaFuncAttributeMaxDynamicSharedMemorySize,
                         SORTMAX * (int)sizeof(u64));
    cudaFuncSetAttribute(reduce_kernel,
                         cudaFuncAttributeMaxDynamicSharedMemorySize,
                         NR * NCHR * (int)sizeof(u64) + 1024);

    passA_kernel<<<1536, 256>>>(cls0, cls1, cls2);
    topk_decode_kernel<<<12, 1024, SORTMAX * sizeof(u64)>>>(cls0, cls1, cls2,
                                                            loc0, loc1, loc2, info);
    mask_kernel<<<dim3(NTRI, NB), 128>>>();
    reduce_kernel<<<NB, 1024, NR * NCHR * sizeof(u64)>>>(out);
}

// round 15
// speedup vs baseline: 1.1570x; 1.1570x over previous
#include <cuda_runtime.h>
#include <math.h>

// ---------------- problem constants ----------------
#define NB    4
#define NLVL  3
#define NA    9
#define NC    80
#define PRE   1000
#define TOPN  100
#define NCAP  8192
#define SPECMAX 2048
#define SORTMAX 4096
#define NR    512         // NMS mask restricted to top-NR rows (exact fallback below)
#define NCHR  8           // NR/64 words
#define MT    4           // NR/128 tiles per dim
#define NTRI  10          // MT*(MT+1)/2
#define LOG_MAX_F 4.135166556742356f
#define IMG_OFF 641.0f

typedef unsigned long long u64;

// Precomputed anchors (verified bit-exact since R5, rel_err 2.455e-8)
__constant__ float c_AW[3][9] = {
    { 44.f,  88.f, 176.f,  32.f,  64.f, 128.f,  24.f,  48.f,  96.f},
    { 92.f, 184.f, 368.f,  64.f, 128.f, 256.f,  44.f,  88.f, 176.f},
    {180.f, 360.f, 720.f, 128.f, 256.f, 512.f,  92.f, 184.f, 368.f}};
__constant__ float c_AH[3][9] = {
    { 24.f,  48.f,  96.f,  32.f,  64.f, 128.f,  48.f,  96.f, 192.f},
    { 48.f,  96.f, 192.f,  64.f, 128.f, 256.f,  88.f, 176.f, 352.f},
    { 88.f, 176.f, 352.f, 128.f, 256.f, 512.f, 184.f, 368.f, 736.f}};
__constant__ float c_ctr[3] = {3.5f, 7.5f, 15.5f};

// ---------------- device scratch (zero at load; re-zeroed each replay by reduce kernel) ----------------
__device__ unsigned int g_cnt  [12];
__device__ unsigned int g_done [12];
__device__ unsigned int g_need [12];
__device__ unsigned int g_mdone[NB];
__device__ u64          g_cand[12][NCAP];
__device__ float        g_rois[NB][3000][6];
__device__ u64          g_skey[NB][3000];
__device__ int          g_spos[NB][3008];
__device__ float        g_sx1[NB][3008], g_sy1[NB][3008], g_sx2[NB][3008], g_sy2[NB][3008], g_sar[NB][3008];
__device__ __align__(16) u64 g_mask[NB][NR * NCHR];

// ---------------- helpers ----------------
__device__ __forceinline__ void bitonic_desc(u64* s, int n, int tid, int nt) {
    for (int k = 2; k <= n; k <<= 1) {
        for (int j = k >> 1; j > 0; j >>= 1) {
            for (int i = tid; i < n; i += nt) {
                int ixj = i ^ j;
                if (ixj > i) {
                    u64 a = s[i], b = s[ixj];
                    bool sw = ((i & k) == 0) ? (a < b) : (a > b);
                    if (sw) { s[i] = b; s[ixj] = a; }
                }
            }
            __syncthreads();
        }
    }
}

template<int HW>
__device__ __forceinline__ void push_cand_t(int id, int m, float x) {
    int ch = m / HW;
    int pp = m - ch * HW;
    int a  = ch / NC;
    int cc = ch - a * NC;
    unsigned int f = (unsigned int)((pp * NA + a) * NC + cc);
    float score = 1.0f / (1.0f + expf(-x));
    u64 k64 = ((u64)__float_as_uint(score) << 32) | (u64)(0xFFFFFFFFu - f);
    unsigned int pos = atomicAdd(&g_cnt[id], 1u);
    if (pos < NCAP) g_cand[id][pos] = k64;
}

__device__ __forceinline__ void push_cand(int id, int m, int HW, float x) {
    int ch = m / HW;
    int pp = m - ch * HW;
    int a  = ch / NC;
    int cc = ch - a * NC;
    unsigned int f = (unsigned int)((pp * NA + a) * NC + cc);
    float score = 1.0f / (1.0f + expf(-x));
    u64 k64 = ((u64)__float_as_uint(score) << 32) | (u64)(0xFFFFFFFFu - f);
    unsigned int pos = atomicAdd(&g_cnt[id], 1u);
    if (pos < NCAP) g_cand[id][pos] = k64;
}

// ---------------- kernel 1: grid-stride full-superblock streaming gather (R13, measured 29.3us) ----------------
template<int LVL, int PER, int NVEC, int HW>
__device__ __forceinline__ void stream_level(const float4* __restrict__ cls, int li, float specT) {
    int b = li / PER;
    int chunk = li - b * PER;
    const float4* p = cls + (size_t)b * NVEC;
    int id = b * 3 + LVL;
    int tid = threadIdx.x;

    constexpr int NS = NVEC / 1024;
    constexpr int REMSTART = NS * 1024;

#pragma unroll 1
    for (int s = chunk; s < NS; s += PER) {
        int i0 = s * 1024;
        float4 v[4];
#pragma unroll
        for (int u = 0; u < 4; u++) v[u] = p[i0 + u * 256 + tid];
#pragma unroll
        for (int u = 0; u < 4; u++) {
            float m4 = fmaxf(fmaxf(v[u].x, v[u].y), fmaxf(v[u].z, v[u].w));
            if (m4 >= specT) {
                int idx = i0 + u * 256 + tid;
                float c[4] = {v[u].x, v[u].y, v[u].z, v[u].w};
#pragma unroll
                for (int q = 0; q < 4; q++)
                    if (c[q] >= specT) push_cand_t<HW>(id, idx * 4 + q, c[q]);
            }
        }
    }
    if (REMSTART < NVEC && chunk == 0) {
        for (int i = REMSTART + tid; i < NVEC; i += 256) {
            float4 v = p[i];
            float c[4] = {v.x, v.y, v.z, v.w};
#pragma unroll
            for (int q = 0; q < 4; q++)
                if (c[q] >= specT) push_cand_t<HW>(id, i * 4 + q, c[q]);
        }
    }

    __syncthreads();
    if (tid == 0) {
        __threadfence();
        unsigned int o = atomicAdd(&g_done[id], 1u);
        if (o == (unsigned int)(PER - 1)) {
            unsigned int cnt = g_cnt[id];
            int ok = (cnt >= PRE && cnt <= SPECMAX);
            g_need[id] = ok ? 0u : 1u;
            if (!ok) g_cnt[id] = 0;
        }
    }
}

__global__ void __launch_bounds__(256)
passA_kernel(const float4* __restrict__ c0,
             const float4* __restrict__ c1,
             const float4* __restrict__ c2) {
    int bx = blockIdx.x;
    if (bx < 1152)      stream_level<0, 288, 1152000, 6400>(c0, bx,        3.42f);
    else if (bx < 1440) stream_level<1, 72,  288000,  1600>(c1, bx - 1152, 3.02f);
    else                stream_level<2, 24,  72000,   400 >(c2, bx - 1440, 2.575f);
}

// ---------------- kernel 2: (rare exact fallback) + sort + fp32 decode + elected merge ----------------
__global__ void topk_decode_kernel(const float4* __restrict__ c0,
                                   const float4* __restrict__ c1,
                                   const float4* __restrict__ c2,
                                   const float* __restrict__ loc0,
                                   const float* __restrict__ loc1,
                                   const float* __restrict__ loc2,
                                   const float* __restrict__ info) {
    extern __shared__ u64 sk[];      // 32KB dynamic
    int lvl = blockIdx.x % 3, b = blockIdx.x / 3;
    int id = b * 3 + lvl;
    int tid = threadIdx.x, nt = blockDim.x;
    const int Wt[3] = {80, 40, 20};
    const int St[3] = {8, 16, 32};
    const int Nv[3] = {1152000, 288000, 72000};
    int W = Wt[lvl], stride = St[lvl];
    const float* loc = (lvl == 0) ? loc0 : ((lvl == 1) ? loc1 : loc2);
    int HW = W * W;

    if (g_need[id] != 0u) {
        unsigned int* hist = (unsigned int*)sk;
        __shared__ unsigned int segsum[256];
        __shared__ unsigned int s_thr;
        int nvec = Nv[lvl];
        const float4* p = ((lvl == 0) ? c0 : ((lvl == 1) ? c1 : c2)) + (size_t)b * nvec;

        for (int i = tid; i < 4096; i += nt) hist[i] = 0;
        __syncthreads();
        for (int i = tid; i < nvec; i += nt) {
            float4 v = p[i];
            float c[4] = {v.x, v.y, v.z, v.w};
#pragma unroll
            for (int q = 0; q < 4; q++) {
                if (c[q] >= 1.0f) {
                    unsigned int key = __float_as_uint(c[q]) | 0x80000000u;
                    atomicAdd(&hist[key >> 20], 1u);
                }
            }
        }
        __syncthreads();
        if (tid < 256) {
            unsigned int s = 0;
#pragma unroll
            for (int q = 0; q < 16; q++) s += hist[tid * 16 + q];
            segsum[tid] = s;
        }
        __syncthreads();
        for (int d = 1; d < 256; d <<= 1) {
            unsigned int v = 0;
            if (tid < 256) {
                v = segsum[tid];
                if (tid + d < 256) v += segsum[tid + d];
            }
            __syncthreads();
            if (tid < 256) segsum[tid] = v;
            __syncthreads();
        }
        if (tid < 256) {
            unsigned int cum = (tid < 255) ? segsum[tid + 1] : 0u;
            for (int q = 15; q >= 0; q--) {
                int bin = tid * 16 + q;
                unsigned int hv = hist[bin];
                cum += hv;
                if (cum >= PRE && (cum - hv) < PRE) s_thr = ((unsigned int)bin) << 20;
            }
        }
        __syncthreads();
        unsigned int thr = s_thr;
        for (int i = tid; i < nvec; i += nt) {
            float4 v = p[i];
            float c[4] = {v.x, v.y, v.z, v.w};
#pragma unroll
            for (int q = 0; q < 4; q++) {
                if (c[q] >= 1.0f) {
                    unsigned int key = __float_as_uint(c[q]) | 0x80000000u;
                    if (key >= thr) push_cand(id, i * 4 + q, HW, c[q]);
                }
            }
        }
        __syncthreads();
    }

    unsigned int cnt = atomicAdd(&g_cnt[id], 0u);
    if (cnt > SORTMAX) cnt = SORTMAX;
    int n = 1024;
    while (n < (int)cnt) n <<= 1;
    for (int i = tid; i < n; i += nt)
        sk[i] = (i < (int)cnt) ? g_cand[id][i] : 0ull;
    __syncthreads();
    bitonic_desc(sk, n, tid, nt);

    float imh = info[b * 5 + 0];
    float imw = info[b * 5 + 1];
    float ctr = c_ctr[lvl];

    for (int r = tid; r < PRE; r += nt) {
        u64 key = sk[r];
        int mpos = lvl * PRE + r;
        float* row = g_rois[b][mpos];
        if (key == 0ull) {
            row[0] = row[1] = row[2] = row[3] = row[4] = row[5] = 0.0f;
            g_skey[b][mpos] = (u64)(0xFFFFFFFFu - (unsigned int)mpos);
            continue;
        }
        unsigned int f = 0xFFFFFFFFu - (unsigned int)(key & 0xFFFFFFFFu);
        float score = __uint_as_float((unsigned int)(key >> 32));
        g_skey[b][mpos] = ((u64)__float_as_uint(score) << 32) |
                          (u64)(0xFFFFFFFFu - (unsigned int)mpos);
        int aidx = f / NC;
        int cc = f - aidx * NC;
        int pp = aidx / NA;
        int a = aidx - pp * NA;
        int hh = pp / W;
        int ww = pp - hh * W;

        float ws = c_AW[lvl][a];
        float hs = c_AH[lvl][a];
        float cx = (float)(ww * stride) + ctr;
        float cy = (float)(hh * stride) + ctr;

        size_t lbase = ((size_t)b * (NA * 4) + (size_t)a * 4) * (size_t)HW + (size_t)pp;
        float dx = loc[lbase];
        float dy = loc[lbase + HW];
        float dw = loc[lbase + 2 * (size_t)HW];
        float dh = loc[lbase + 3 * (size_t)HW];

        dw = fminf(fmaxf(dw, -LOG_MAX_F), LOG_MAX_F);
        dh = fminf(fmaxf(dh, -LOG_MAX_F), LOG_MAX_F);
        float pcx = dx * ws + cx, pcy = dy * hs + cy;
        float pw = expf(dw) * ws, ph = expf(dh) * hs;
        float x1 = pcx - 0.5f * (pw - 1.0f);
        float y1 = pcy - 0.5f * (ph - 1.0f);
        float x2 = pcx + 0.5f * (pw - 1.0f);
        float y2 = pcy + 0.5f * (ph - 1.0f);
        x1 = fminf(fmaxf(x1, 0.0f), imw - 1.0f);
        y1 = fminf(fmaxf(y1, 0.0f), imh - 1.0f);
        x2 = fminf(fmaxf(x2, 0.0f), imw - 1.0f);
        y2 = fminf(fmaxf(y2, 0.0f), imh - 1.0f);

        row[0] = x1; row[1] = y1; row[2] = x2; row[3] = y2;
        row[4] = score;
        row[5] = (float)(cc + 1);
    }

    __syncthreads();
    __shared__ int s_lastm;
    if (tid == 0) {
        __threadfence();
        unsigned int o = atomicAdd(&g_mdone[b], 1u);
        s_lastm = (o == 2u);
    }
    __syncthreads();
    if (!s_lastm) return;
    __threadfence();

    u64* A = sk;
    for (int i = tid; i < 3000; i += nt) A[i] = g_skey[b][i];
    __syncthreads();
    for (int i = tid; i < 3000; i += nt) {
        u64 k = A[i];
        int l = i / 1000;
        int r = i - l * 1000;
        int rank = r;
#pragma unroll
        for (int o = 0; o < 3; o++) {
            if (o == l) continue;
            const u64* arr = &A[o * 1000];
            int lo = 0, hi = 1000;
            while (lo < hi) {
                int mid = (lo + hi) >> 1;
                if (arr[mid] > k) lo = mid + 1; else hi = mid;
            }
            rank += lo;
        }
        g_spos[b][rank] = i;
        const float* rw = g_rois[b][i];
        float off = rw[5] * IMG_OFF;
        float a1 = rw[0] + off, b1 = rw[1] + off;
        float a2 = rw[2] + off, b2 = rw[3] + off;
        g_sx1[b][rank] = a1; g_sy1[b][rank] = b1;
        g_sx2[b][rank] = a2; g_sy2[b][rank] = b2;
        g_sar[b][rank] = (a2 - a1 + 1.0f) * (b2 - b1 + 1.0f);
    }
}

// ---------------- kernel 3: lean suppression bitmask over top-NR rows (dense packing) ----------------
__global__ void __launch_bounds__(128) mask_kernel() {
    int b = blockIdx.y;
    int t = blockIdx.x;
    int tr = 0;
    while (t >= MT - tr) { t -= MT - tr; tr++; }
    int tc = tr + t;
    int tid = threadIdx.x;

    __shared__ float sx1[128], sy1[128], sx2[128], sy2[128], sar[128];
    int col0 = tc * 128;
    int c = col0 + tid;
    sx1[tid] = g_sx1[b][c];
    sy1[tid] = g_sy1[b][c];
    sx2[tid] = g_sx2[b][c];
    sy2[tid] = g_sy2[b][c];
    sar[tid] = g_sar[b][c];
    __syncthreads();

    int row = tr * 128 + tid;
    float X1 = g_sx1[b][row], Y1 = g_sy1[b][row];
    float X2 = g_sx2[b][row], Y2 = g_sy2[b][row];
    float AR = g_sar[b][row];
    u64 bits0 = 0ull, bits1 = 0ull;
#pragma unroll 4
    for (int j = 0; j < 128; j++) {
        int cidx = col0 + j;
        if (cidx <= row) continue;
        float ltx = fmaxf(X1, sx1[j]);
        float lty = fmaxf(Y1, sy1[j]);
        float rbx = fminf(X2, sx2[j]);
        float rby = fminf(Y2, sy2[j]);
        float w = fmaxf((rbx - ltx) + 1.0f, 0.0f);
        float h = fmaxf((rby - lty) + 1.0f, 0.0f);
        float inter = w * h;
        float iou = inter / ((AR + sar[j]) - inter);
        if (iou > 0.5f) {
            if (j < 64) bits0 |= (1ull << j);
            else        bits1 |= (1ull << (j - 64));
        }
    }
    int ci0 = 2 * tc;
    g_mask[b][row * NCHR + ci0]     = bits0;
    g_mask[b][row * NCHR + ci0 + 1] = bits1;
}

// ---------------- kernel 4: smem-staged broadcast-LDS greedy scan + fallback + rezero ----------------
__global__ void __launch_bounds__(1024) reduce_kernel(float* __restrict__ out) {
    extern __shared__ u64 smask[];        // NR*NCHR u64 = 32KB dynamic
    int b = blockIdx.x, tid = threadIdx.x;

    {
        const ulonglong2* src = (const ulonglong2*)g_mask[b];
        ulonglong2* dst = (ulonglong2*)smask;
        for (int i = tid; i < NR * NCHR / 2; i += 1024)
            dst[i] = src[i];
    }
    __syncthreads();

    __shared__ int kept[TOPN];
    __shared__ int s_k;

    // warp-0 greedy scan; broadcast-LDS keeps SHFL off the per-kept critical path
    if (tid < 32) {
        const unsigned FULL = 0xFFFFFFFFu;
        int lane = tid;
        u64 myremv = 0ull;   // lane w (<NCHR) accumulates suppression word w
        int k = 0;
        for (int w = 0; w < NCHR && k < TOPN; w++) {
            u64 avail = ~__shfl_sync(FULL, myremv, w);
            while (avail && k < TOPN) {
                int j = __ffsll((long long)avail) - 1;
                int i = w * 64 + j;
                kept[k] = i;
                k++;
                if (k == TOPN) break;
                u64 diagw = smask[(size_t)i * NCHR + w];
                u64 roww = (lane < NCHR) ? smask[(size_t)i * NCHR + lane] : 0ull;
                myremv |= roww;
                avail &= ~(1ull << j);
                avail &= ~diagw;
            }
        }
        if (lane == 0) s_k = k;
    }
    __syncthreads();
    int k = s_k;

    if (k == TOPN) {
        for (int r = tid; r < TOPN; r += 1024) {
            float* o = out + ((size_t)b * TOPN + r) * 7;
            int pos = g_spos[b][kept[r]];
            const float* rw = g_rois[b][pos];
            o[0] = (float)b;
            o[1] = rw[0]; o[2] = rw[1]; o[3] = rw[2]; o[4] = rw[3];
            o[5] = rw[4]; o[6] = rw[5];
        }
    } else {
        // exact full serial NMS over all 3000 (guaranteed path; statistically never taken)
        __shared__ unsigned char supp[3000];
        __shared__ int fkept[TOPN];
        __shared__ int s_i, s_k2, s_cur;
        for (int i = tid; i < 3000; i += 1024) supp[i] = 0;
        if (tid == 0) { s_i = 0; s_k2 = 0; }
        __syncthreads();
        for (;;) {
            if (tid == 0) {
                int i = s_i;
                while (i < 3000 && supp[i]) i++;
                if (i < 3000 && s_k2 < TOPN) {
                    fkept[s_k2] = i; s_k2++; s_i = i + 1; s_cur = i;
                } else s_cur = -1;
            }
            __syncthreads();
            int i = s_cur;
            if (i < 0) break;
            if (s_k2 >= TOPN) break;
            float X1 = g_sx1[b][i], Y1 = g_sy1[b][i];
            float X2 = g_sx2[b][i], Y2 = g_sy2[b][i], AR = g_sar[b][i];
            for (int j = i + 1 + tid; j < 3000; j += 1024) {
                if (supp[j]) continue;
                float ltx = fmaxf(X1, g_sx1[b][j]);
                float lty = fmaxf(Y1, g_sy1[b][j]);
                float rbx = fminf(X2, g_sx2[b][j]);
                float rby = fminf(Y2, g_sy2[b][j]);
                float w = fmaxf((rbx - ltx) + 1.0f, 0.0f);
                float h = fmaxf((rby - lty) + 1.0f, 0.0f);
                float inter = w * h;
                float iou = inter / ((AR + g_sar[b][j]) - inter);
                if (iou > 0.5f) supp[j] = 1;
            }
            __syncthreads();
        }
        __syncthreads();
        for (int r = tid; r < TOPN; r += 1024) {
            float* o = out + ((size_t)b * TOPN + r) * 7;
            if (r < s_k2) {
                int pos = g_spos[b][fkept[r]];
                const float* rw = g_rois[b][pos];
                o[0] = (float)b;
                o[1] = rw[0]; o[2] = rw[1]; o[3] = rw[2]; o[4] = rw[3];
                o[5] = rw[4]; o[6] = rw[5];
            } else {
                for (int q = 0; q < 7; q++) o[q] = 0.0f;
            }
        }
        __syncthreads();
    }

    // re-zero counters for next graph replay
    if (tid == 0) {
        g_mdone[b] = 0;
#pragma unroll
        for (int l = 0; l < 3; l++) {
            g_cnt[b * 3 + l] = 0;
            g_done[b * 3 + l] = 0;
            g_need[b * 3 + l] = 0;
        }
    }
}

// ---------------- host launcher ----------------
extern "C" void kernel_launch(void* const* d_in, const int* in_sizes, int n_in,
                              void* d_out, int out_size) {
    (void)in_sizes; (void)n_in; (void)out_size;
    const float4* cls0 = (const float4*)d_in[0];
    const float*  loc0 = (const float*)d_in[1];
    const float4* cls1 = (const float4*)d_in[2];
    const float*  loc1 = (const float*)d_in[3];
    const float4* cls2 = (const float4*)d_in[4];
    const float*  loc2 = (const float*)d_in[5];
    const float*  info = (const float*)d_in[6];
    float* out = (float*)d_out;

    cudaFuncSetAttribute(topk_decode_kernel,
                         cudaFuncAttributeMaxDynamicSharedMemorySize,
                         SORTMAX * (int)sizeof(u64));
    cudaFuncSetAttribute(reduce_kernel,
                         cudaFuncAttributeMaxDynamicSharedMemorySize,
                         NR * NCHR * (int)sizeof(u64) + 1024);

    passA_kernel<<<1536, 256>>>(cls0, cls1, cls2);
    topk_decode_kernel<<<12, 1024, SORTMAX * sizeof(u64)>>>(cls0, cls1, cls2,
                                                            loc0, loc1, loc2, info);
    mask_kernel<<<dim3(NTRI, NB), 128>>>();
    reduce_kernel<<<NB, 1024, NR * NCHR * sizeof(u64)>>>(out);
}